// round 9
// baseline (speedup 1.0000x reference)
#include <cuda_runtime.h>
#include <cstdint>
#include <math.h>

#define NN 250000
#define EE 250000
#define D   128
#define HID 256
#define NT  512
#define BR  64
#define KC  32
#define XS  34            // conflict-free stride for LDS.64
#define HS  258

// ---- persistent device scratch ----
__device__ float g_Sp[(size_t)NN * D];   // zero-init; kept zeroed by aggr kernel
__device__ float g_Sc[(size_t)NN * D];
__device__ int   g_cnt[2 * NN];
__device__ float g_inv[2 * NN];
__device__ float g_edge[2 * D];          // [0:128)=edge_in, [128:256)=edge_out
__device__ float g_b1P[HID];
__device__ float g_b1C[HID];

__device__ __forceinline__ void ffma2(uint64_t& acc, uint64_t x, uint64_t w) {
    asm("fma.rn.f32x2 %0, %1, %2, %0;" : "+l"(acc) : "l"(x), "l"(w));
}
__device__ __forceinline__ float sum2(uint64_t v) {
    uint32_t lo, hi;
    asm("mov.b64 {%0,%1}, %2;" : "=r"(lo), "=r"(hi) : "l"(v));
    return __uint_as_float(lo) + __uint_as_float(hi);
}
__device__ __forceinline__ void redadd(float* p, float v) {
    asm volatile("red.global.add.f32 [%0], %1;" :: "l"(p), "f"(v) : "memory");
}

// ---------------- setup kernels (identical to the passing R4 kernel) ----------------
__global__ void edge_const_k(const float* __restrict__ Ew1, const float* __restrict__ Eb1,
                             const float* __restrict__ Ew2, const float* __restrict__ Eb2) {
    __shared__ float hin[HID], hout[HID];
    int t = threadIdx.x;
    hin[t]  = fmaxf(Ew1[t] + Eb1[t], 0.f);
    hout[t] = fmaxf(Eb1[t], 0.f);
    __syncthreads();
    if (t < D) {
        float si = 0.f, so = 0.f;
        for (int j = 0; j < HID; j++) { float w = Ew2[j * D + t]; si += hin[j] * w; so += hout[j] * w; }
        g_edge[t]     = fmaxf(si + Eb2[t], 0.f);   // edge_in
        g_edge[D + t] = fmaxf(so + Eb2[t], 0.f);   // edge_out
    }
}
__global__ void fold_bias_k(const float* __restrict__ Pw1, const float* __restrict__ Pb1,
                            const float* __restrict__ Cw1, const float* __restrict__ Cb1) {
    int j = threadIdx.x;  // 256
    float sp = Pb1[j], sc = Cb1[j];
    for (int c = 0; c < D; c++) {
        sp += g_edge[D + c] * Pw1[(size_t)(2 * D + c) * HID + j];  // edge_out -> P
        sc += g_edge[c]     * Cw1[(size_t)(2 * D + c) * HID + j];  // edge_in  -> C
    }
    g_b1P[j] = sp; g_b1C[j] = sc;
}
__global__ void zero_cnt_k() {
    int i = blockIdx.x * blockDim.x + threadIdx.x;
    if (i < 2 * NN) g_cnt[i] = 0;
}
__global__ void count_k(const int* __restrict__ si, const int* __restrict__ pi) {
    int e = blockIdx.x * blockDim.x + threadIdx.x;
    if (e < EE) { atomicAdd(&g_cnt[si[e]], 1); atomicAdd(&g_cnt[NN + pi[e]], 1); }
}
__global__ void inv_k() {
    int i = blockIdx.x * blockDim.x + threadIdx.x;
    if (i < 2 * NN) g_inv[i] = 1.f / fmaxf((float)g_cnt[i], 1.f);
}

// ---------------------------------------------------------------------------
// Fused 2-layer MLP, f32x2 micro-kernel — R4 logic, restructured ONLY for
// 512 threads (16 warps, 4 rows/warp). Staging, finalize, scatter identical.
// MODE 0: X = srcA rows;                         out: dst = y
// MODE 1: X = [hid[idxA], hid[idxB]] (K=256);    out: red-scatter by sidx
// MODE 2: X = [hid, Sp*inv+rm*st, Sc*inv+lm*et]; out: dst += y; re-zero Sp/Sc
// ---------------------------------------------------------------------------
template <int KIN, int MODE, int TGT>
__global__ __launch_bounds__(NT, 1) void mlp2_k(
    int rows,
    const float* __restrict__ W1, const float* __restrict__ B1a,
    const float* __restrict__ W2, const float* __restrict__ B2,
    const float* __restrict__ srcA,
    const int* __restrict__ idxA, const int* __restrict__ idxB, const int* __restrict__ sidx,
    const float* __restrict__ rmask, const float* __restrict__ lmask,
    const float* __restrict__ stok,  const float* __restrict__ etok,
    float* __restrict__ dst)
{
    extern __shared__ float sm[];
    float* Xs  = sm;                     // BR x XS
    float* Wst = Xs + BR * XS;           // 256 x XS (transposed weight chunk)
    float* Hs  = Wst + HID * XS;         // BR x HS

    const float* B1 = (MODE == 1) ? (TGT == 0 ? (const float*)g_b1P : (const float*)g_b1C) : B1a;
    const int tid  = threadIdx.x;
    const int wid  = tid >> 5, lane = tid & 31;
    const int row0 = blockIdx.x * BR;

    // ---------------- phase A: H = relu(X @ W1 + b1), N=256 ----------------
    uint64_t acc[4][8];
#pragma unroll
    for (int i = 0; i < 4; i++)
#pragma unroll
        for (int m = 0; m < 8; m++) acc[i][m] = 0ull;

    for (int kc = 0; kc < KIN; kc += KC) {
        // stage X tile [64][32] (k contiguous) — identical value computation to R4
#pragma unroll
        for (int i = 0; i < 4; i++) {
            int e = i * NT + tid;
            int r = e >> 5, cc = e & 31;
            int gr = row0 + r; if (gr >= rows) gr = rows - 1;
            int col = kc + cc;
            float v;
            if (MODE == 0) {
                v = srcA[(size_t)gr * D + col];
            } else if (MODE == 1) {
                int c2 = col & 127;
                int idx = (col < 128 ? idxA : idxB)[gr];
                v = srcA[(size_t)idx * D + c2];
            } else {
                int c2 = col & 127;
                if (col < 128)      v = srcA[(size_t)gr * D + c2];
                else if (col < 256) v = g_Sp[(size_t)gr * D + c2] * g_inv[gr]      + rmask[gr] * stok[c2];
                else                v = g_Sc[(size_t)gr * D + c2] * g_inv[NN + gr] + lmask[gr] * etok[c2];
            }
            Xs[r * XS + cc] = v;
        }
        // stage W1 chunk transposed: Wst[n][kk] = W1[kc+kk][n]
#pragma unroll
        for (int i = 0; i < 16; i++) {
            int e = i * NT + tid;
            int kk = e >> 8, n = e & 255;
            Wst[n * XS + kk] = W1[(size_t)(kc + kk) * HID + n];
        }
        __syncthreads();
#pragma unroll
        for (int kp = 0; kp < 16; kp++) {
            uint64_t xp[4];
#pragma unroll
            for (int i = 0; i < 4; i++)
                xp[i] = *(const uint64_t*)&Xs[(wid * 4 + i) * XS + kp * 2];
#pragma unroll
            for (int m = 0; m < 8; m++) {
                uint64_t wv = *(const uint64_t*)&Wst[(m * 32 + lane) * XS + kp * 2];
#pragma unroll
                for (int i = 0; i < 4; i++) ffma2(acc[i][m], xp[i], wv);
            }
        }
        __syncthreads();
    }

    if (MODE == 2) {   // re-zero consumed Sp/Sc rows (block-exclusive, replay-invariant)
        float4 z = make_float4(0.f, 0.f, 0.f, 0.f);
        for (int i = tid; i < BR * 32; i += NT) {
            int gr = row0 + (i >> 5);
            if (gr < rows) {
                ((float4*)g_Sp)[(size_t)gr * 32 + (i & 31)] = z;
                ((float4*)g_Sc)[(size_t)gr * 32 + (i & 31)] = z;
            }
        }
    }

    // epilogue A -> Hs
#pragma unroll
    for (int m = 0; m < 8; m++) {
        int col = m * 32 + lane;
        float b = B1[col];
#pragma unroll
        for (int i = 0; i < 4; i++)
            Hs[(wid * 4 + i) * HS + col] = fmaxf(sum2(acc[i][m]) + b, 0.f);
    }
    __syncthreads();

    // ---------------- phase B: Y = relu(H @ W2 + b2), N=128 ----------------
    uint64_t acc2[4][4];
#pragma unroll
    for (int i = 0; i < 4; i++)
#pragma unroll
        for (int m = 0; m < 4; m++) acc2[i][m] = 0ull;

    for (int kc = 0; kc < HID; kc += KC) {
#pragma unroll
        for (int i = 0; i < 8; i++) {
            int e = i * NT + tid;
            int kk = e >> 7, n = e & 127;
            Wst[n * XS + kk] = W2[(size_t)(kc + kk) * D + n];
        }
        __syncthreads();
#pragma unroll
        for (int kp = 0; kp < 16; kp++) {
            uint64_t xp[4];
#pragma unroll
            for (int i = 0; i < 4; i++)
                xp[i] = *(const uint64_t*)&Hs[(wid * 4 + i) * HS + kc + kp * 2];
#pragma unroll
            for (int m = 0; m < 4; m++) {
                uint64_t wv = *(const uint64_t*)&Wst[(m * 32 + lane) * XS + kp * 2];
#pragma unroll
                for (int i = 0; i < 4; i++) ffma2(acc2[i][m], xp[i], wv);
            }
        }
        __syncthreads();
    }

    // ---------------- epilogue B ----------------
#pragma unroll
    for (int i = 0; i < 4; i++) {
        int gr = row0 + wid * 4 + i;
        if (gr >= rows) continue;
        int t = 0;
        if (MODE == 1) t = sidx[gr];
#pragma unroll
        for (int m = 0; m < 4; m++) {
            int col = m * 32 + lane;
            float y = fmaxf(sum2(acc2[i][m]) + B2[col], 0.f);
            if (MODE == 1) {
                redadd((TGT == 0 ? g_Sp : g_Sc) + (size_t)t * D + col, y);
            } else if (MODE == 0) {
                dst[(size_t)gr * D + col] = y;
            } else {
                size_t o = (size_t)gr * D + col;
                dst[o] = dst[o] + y;
            }
        }
    }
}

// ---------------------------------------------------------------------------
extern "C" void kernel_launch(void* const* d_in, const int* in_sizes, int n_in,
                              void* d_out, int out_size) {
    const float* bt    = (const float*)d_in[0];
    const int*   si    = (const int*)  d_in[1];
    const int*   pi    = (const int*)  d_in[2];
    const float* rmask = (const float*)d_in[3];
    const float* lmask = (const float*)d_in[4];
    const float* stok  = (const float*)d_in[5];
    const float* etok  = (const float*)d_in[6];
    const float* Vw1 = (const float*)d_in[7],  *Vb1 = (const float*)d_in[8];
    const float* Vw2 = (const float*)d_in[9],  *Vb2 = (const float*)d_in[10];
    const float* Ew1 = (const float*)d_in[11], *Eb1 = (const float*)d_in[12];
    const float* Ew2 = (const float*)d_in[13], *Eb2 = (const float*)d_in[14];
    const float* Pw1 = (const float*)d_in[15], *Pb1 = (const float*)d_in[16];
    const float* Pw2 = (const float*)d_in[17], *Pb2 = (const float*)d_in[18];
    const float* Cw1 = (const float*)d_in[19], *Cb1 = (const float*)d_in[20];
    const float* Cw2 = (const float*)d_in[21], *Cb2 = (const float*)d_in[22];
    const float* Aw1 = (const float*)d_in[23], *Ab1 = (const float*)d_in[24];
    const float* Aw2 = (const float*)d_in[25], *Ab2 = (const float*)d_in[26];
    float* hid = (float*)d_out;

    const int smem = (BR * XS + HID * XS + BR * HS) * (int)sizeof(float);
    cudaFuncSetAttribute(mlp2_k<128, 0, 0>, cudaFuncAttributeMaxDynamicSharedMemorySize, smem);
    cudaFuncSetAttribute(mlp2_k<256, 1, 0>, cudaFuncAttributeMaxDynamicSharedMemorySize, smem);
    cudaFuncSetAttribute(mlp2_k<256, 1, 1>, cudaFuncAttributeMaxDynamicSharedMemorySize, smem);
    cudaFuncSetAttribute(mlp2_k<384, 2, 0>, cudaFuncAttributeMaxDynamicSharedMemorySize, smem);

    edge_const_k<<<1, 256>>>(Ew1, Eb1, Ew2, Eb2);
    fold_bias_k<<<1, 256>>>(Pw1, Pb1, Cw1, Cb1);
    zero_cnt_k<<<(2 * NN + 255) / 256, 256>>>();
    count_k<<<(EE + 255) / 256, 256>>>(si, pi);
    inv_k<<<(2 * NN + 255) / 256, 256>>>();

    const int gb = (NN + BR - 1) / BR;

    // hidden = MLP_V(batch_token)
    mlp2_k<128, 0, 0><<<gb, NT, smem>>>(NN, Vw1, Vb1, Vw2, Vb2, bt,
                                        nullptr, nullptr, nullptr,
                                        nullptr, nullptr, nullptr, nullptr, hid);
    for (int h = 0; h < 3; h++) {
        // S_p += MLP_P([hid[parent], hid[self]]) scattered by self (edge folded into bias)
        mlp2_k<256, 1, 0><<<gb, NT, smem>>>(EE, Pw1, nullptr, Pw2, Pb2, hid,
                                            pi, si, si,
                                            nullptr, nullptr, nullptr, nullptr, nullptr);
        // S_c += MLP_C([hid[self], hid[parent]]) scattered by parent
        mlp2_k<256, 1, 1><<<gb, NT, smem>>>(EE, Cw1, nullptr, Cw2, Cb2, hid,
                                            si, pi, pi,
                                            nullptr, nullptr, nullptr, nullptr, nullptr);
        // hidden += MLP_A([hid, Sp*inv + rm*st, Sc*inv + lm*et]); re-zeros Sp/Sc
        mlp2_k<384, 2, 0><<<gb, NT, smem>>>(NN, Aw1, Ab1, Aw2, Ab2, hid,
                                            nullptr, nullptr, nullptr,
                                            rmask, lmask, stok, etok, hid);
    }
}

// round 10
// speedup vs baseline: 1.1808x; 1.1808x over previous
#include <cuda_runtime.h>
#include <cstdint>
#include <math.h>

#define NN 250000
#define EE 250000
#define D   128
#define HID 256
#define NT  256
#define BR  64
#define KC  32
#define XS  34            // conflict-free stride for LDS.64
#define HS  258

// ---- persistent device scratch ----
__device__ float g_Sp[(size_t)NN * D];   // zero-init; kept zeroed by aggr kernel
__device__ float g_Sc[(size_t)NN * D];
__device__ int   g_cnt[2 * NN];
__device__ float g_inv[2 * NN];
__device__ float g_edge[2 * D];          // [0:128)=edge_in, [128:256)=edge_out
__device__ float g_b1P[HID];
__device__ float g_b1C[HID];
// transposed weights [N][K]
__device__ float g_w1tV[256 * 128];
__device__ float g_w1tP[256 * 256];
__device__ float g_w1tC[256 * 256];
__device__ float g_w1tA[256 * 384];
__device__ float g_w2tV[128 * 256];
__device__ float g_w2tP[128 * 256];
__device__ float g_w2tC[128 * 256];
__device__ float g_w2tA[128 * 256];

__device__ __forceinline__ void ffma2(uint64_t& acc, uint64_t x, uint64_t w) {
    asm("fma.rn.f32x2 %0, %1, %2, %0;" : "+l"(acc) : "l"(x), "l"(w));
}
__device__ __forceinline__ float sum2(uint64_t v) {
    uint32_t lo, hi;
    asm("mov.b64 {%0,%1}, %2;" : "=r"(lo), "=r"(hi) : "l"(v));
    return __uint_as_float(lo) + __uint_as_float(hi);
}
__device__ __forceinline__ void redadd(float* p, float v) {
    asm volatile("red.global.add.f32 [%0], %1;" :: "l"(p), "f"(v) : "memory");
}

// ---------------- setup kernels ----------------
__global__ void edge_const_k(const float* __restrict__ Ew1, const float* __restrict__ Eb1,
                             const float* __restrict__ Ew2, const float* __restrict__ Eb2) {
    __shared__ float hin[HID], hout[HID];
    int t = threadIdx.x;
    hin[t]  = fmaxf(Ew1[t] + Eb1[t], 0.f);
    hout[t] = fmaxf(Eb1[t], 0.f);
    __syncthreads();
    if (t < D) {
        float si = 0.f, so = 0.f;
        for (int j = 0; j < HID; j++) { float w = Ew2[j * D + t]; si += hin[j] * w; so += hout[j] * w; }
        g_edge[t]     = fmaxf(si + Eb2[t], 0.f);   // edge_in
        g_edge[D + t] = fmaxf(so + Eb2[t], 0.f);   // edge_out
    }
}
__global__ void fold_bias_k(const float* __restrict__ Pw1, const float* __restrict__ Pb1,
                            const float* __restrict__ Cw1, const float* __restrict__ Cb1) {
    int j = threadIdx.x;  // 256
    float sp = Pb1[j], sc = Cb1[j];
    for (int c = 0; c < D; c++) {
        sp += g_edge[D + c] * Pw1[(size_t)(2 * D + c) * HID + j];  // edge_out -> P
        sc += g_edge[c]     * Cw1[(size_t)(2 * D + c) * HID + j];  // edge_in  -> C
    }
    g_b1P[j] = sp; g_b1C[j] = sc;
}
__global__ void zero_cnt_k() {
    int i = blockIdx.x * blockDim.x + threadIdx.x;
    if (i < 2 * NN) g_cnt[i] = 0;
}
__global__ void count_k(const int* __restrict__ si, const int* __restrict__ pi) {
    int e = blockIdx.x * blockDim.x + threadIdx.x;
    if (e < EE) { atomicAdd(&g_cnt[si[e]], 1); atomicAdd(&g_cnt[NN + pi[e]], 1); }
}
__global__ void inv_k() {
    int i = blockIdx.x * blockDim.x + threadIdx.x;
    if (i < 2 * NN) g_inv[i] = 1.f / fmaxf((float)g_cnt[i], 1.f);
}
// W1 [K][256] -> W1T [256][K]   (dst selected IN DEVICE CODE — no host symbol args)
__global__ void prep_w1_k(const float* __restrict__ W, int K, int id) {
    float* dst = id == 0 ? g_w1tV : id == 1 ? g_w1tP : id == 2 ? g_w1tC : g_w1tA;
    int i = blockIdx.x * blockDim.x + threadIdx.x;
    if (i < K * 256) { int k = i >> 8, n = i & 255; dst[(size_t)n * K + k] = W[i]; }
}
// W2 [256][128] -> W2T [128][256]
__global__ void prep_w2_k(const float* __restrict__ W, int id) {
    float* dst = id == 0 ? g_w2tV : id == 1 ? g_w2tP : id == 2 ? g_w2tC : g_w2tA;
    int i = blockIdx.x * blockDim.x + threadIdx.x;
    if (i < 256 * 128) { int k = i >> 7, n = i & 127; dst[(size_t)n * 256 + k] = W[i]; }
}

// ---------------------------------------------------------------------------
// Fused 2-layer MLP, f32x2 micro-kernel — R4 compute shape (256 thr, 8 rows/warp),
// staging now COALESCED float2 from pre-transposed weights.
// MODE 0: X = srcA rows;                         out: dst = y
// MODE 1: X = [hid[idxA], hid[idxB]] (K=256);    out: red-scatter by sidx
// MODE 2: X = [hid, Sp*inv+rm*st, Sc*inv+lm*et]; out: dst += y; re-zero Sp/Sc
// ---------------------------------------------------------------------------
template <int KIN, int MODE, int TGT>
__global__ __launch_bounds__(NT, 1) void mlp5_k(
    int rows,
    const float* __restrict__ B1a, const float* __restrict__ B2,
    const float* __restrict__ srcA,
    const int* __restrict__ idxA, const int* __restrict__ idxB, const int* __restrict__ sidx,
    const float* __restrict__ rmask, const float* __restrict__ lmask,
    const float* __restrict__ stok,  const float* __restrict__ etok,
    float* __restrict__ dst)
{
    extern __shared__ float sm[];
    float* Xs  = sm;                     // BR x XS
    float* Wst = Xs + BR * XS;           // 256 x XS
    float* Hs  = Wst + HID * XS;         // BR x HS

    const float* W1T = MODE == 0 ? g_w1tV : MODE == 2 ? g_w1tA : (TGT == 0 ? g_w1tP : g_w1tC);
    const float* W2T = MODE == 0 ? g_w2tV : MODE == 2 ? g_w2tA : (TGT == 0 ? g_w2tP : g_w2tC);
    const float* B1  = (MODE == 1) ? (TGT == 0 ? (const float*)g_b1P : (const float*)g_b1C) : B1a;

    const int tid  = threadIdx.x;
    const int wid  = tid >> 5, lane = tid & 31;
    const int row0 = blockIdx.x * BR;

    // ---------------- phase A: H = relu(X @ W1 + b1), N=256 ----------------
    uint64_t acc[8][8];
#pragma unroll
    for (int i = 0; i < 8; i++)
#pragma unroll
        for (int m = 0; m < 8; m++) acc[i][m] = 0ull;

    for (int kc = 0; kc < KIN; kc += KC) {
        // X tile: 64 rows x 16 float2 (coalesced / fused gather)
#pragma unroll
        for (int i = 0; i < 4; i++) {
            int e = i * NT + tid;
            int r = e >> 4, s = e & 15;
            int gr = row0 + r; if (gr >= rows) gr = rows - 1;
            int col = kc + s * 2;
            float2 v;
            if (MODE == 0) {
                v = *(const float2*)(srcA + (size_t)gr * D + col);
            } else if (MODE == 1) {
                int idx = (col < 128 ? idxA : idxB)[gr];
                v = *(const float2*)(srcA + (size_t)idx * D + (col & 127));
            } else {
                if (col < 128) {
                    v = *(const float2*)(srcA + (size_t)gr * D + col);
                } else {
                    const float* S; const float* tok; float iv, m;
                    if (col < 256) { S = g_Sp; tok = stok; iv = g_inv[gr];      m = rmask[gr]; }
                    else           { S = g_Sc; tok = etok; iv = g_inv[NN + gr]; m = lmask[gr]; }
                    int c2 = col & 127;
                    float2 s2 = *(const float2*)(S + (size_t)gr * D + c2);
                    float2 t2 = *(const float2*)(tok + c2);
                    v.x = fmaf(s2.x, iv, m * t2.x);
                    v.y = fmaf(s2.y, iv, m * t2.y);
                }
            }
            *(float2*)&Xs[r * XS + s * 2] = v;
        }
        // W1 chunk: 256 n x 16 float2, coalesced from transposed gmem
#pragma unroll
        for (int i = 0; i < 16; i++) {
            int e = i * NT + tid;
            int n = e >> 4, s = e & 15;
            *(float2*)&Wst[n * XS + s * 2] =
                *(const float2*)(W1T + (size_t)n * KIN + kc + s * 2);
        }
        __syncthreads();
#pragma unroll
        for (int kp = 0; kp < 16; kp++) {
            uint64_t xp[8];
#pragma unroll
            for (int i = 0; i < 8; i++)
                xp[i] = *(const uint64_t*)&Xs[(wid * 8 + i) * XS + kp * 2];
#pragma unroll
            for (int m = 0; m < 8; m++) {
                uint64_t wv = *(const uint64_t*)&Wst[(m * 32 + lane) * XS + kp * 2];
#pragma unroll
                for (int i = 0; i < 8; i++) ffma2(acc[i][m], xp[i], wv);
            }
        }
        __syncthreads();
    }

    if (MODE == 2) {   // re-zero consumed Sp/Sc rows (block-exclusive, replay-invariant)
        float4 z = make_float4(0.f, 0.f, 0.f, 0.f);
        for (int i = tid; i < BR * 32; i += NT) {
            int gr = row0 + (i >> 5);
            if (gr < rows) {
                ((float4*)g_Sp)[(size_t)gr * 32 + (i & 31)] = z;
                ((float4*)g_Sc)[(size_t)gr * 32 + (i & 31)] = z;
            }
        }
    }

    // epilogue A -> Hs
#pragma unroll
    for (int m = 0; m < 8; m++) {
        int col = m * 32 + lane;
        float b = B1[col];
#pragma unroll
        for (int i = 0; i < 8; i++)
            Hs[(wid * 8 + i) * HS + col] = fmaxf(sum2(acc[i][m]) + b, 0.f);
    }
    __syncthreads();

    // ---------------- phase B: Y = relu(H @ W2 + b2), N=128 ----------------
    uint64_t acc2[8][4];
#pragma unroll
    for (int i = 0; i < 8; i++)
#pragma unroll
        for (int m = 0; m < 4; m++) acc2[i][m] = 0ull;

    for (int kc = 0; kc < HID; kc += KC) {
#pragma unroll
        for (int i = 0; i < 8; i++) {
            int e = i * NT + tid;
            int n = e >> 4, s = e & 15;
            *(float2*)&Wst[n * XS + s * 2] =
                *(const float2*)(W2T + (size_t)n * 256 + kc + s * 2);
        }
        __syncthreads();
#pragma unroll
        for (int kp = 0; kp < 16; kp++) {
            uint64_t xp[8];
#pragma unroll
            for (int i = 0; i < 8; i++)
                xp[i] = *(const uint64_t*)&Hs[(wid * 8 + i) * HS + kc + kp * 2];
#pragma unroll
            for (int m = 0; m < 4; m++) {
                uint64_t wv = *(const uint64_t*)&Wst[(m * 32 + lane) * XS + kp * 2];
#pragma unroll
                for (int i = 0; i < 8; i++) ffma2(acc2[i][m], xp[i], wv);
            }
        }
        __syncthreads();
    }

    // ---------------- epilogue B ----------------
#pragma unroll
    for (int i = 0; i < 8; i++) {
        int gr = row0 + wid * 8 + i;
        if (gr >= rows) continue;
        int t = 0;
        if (MODE == 1) t = sidx[gr];
#pragma unroll
        for (int m = 0; m < 4; m++) {
            int col = m * 32 + lane;
            float y = fmaxf(sum2(acc2[i][m]) + B2[col], 0.f);
            if (MODE == 1) {
                redadd((TGT == 0 ? g_Sp : g_Sc) + (size_t)t * D + col, y);
            } else if (MODE == 0) {
                dst[(size_t)gr * D + col] = y;
            } else {
                size_t o = (size_t)gr * D + col;
                dst[o] = dst[o] + y;
            }
        }
    }
}

// ---------------------------------------------------------------------------
extern "C" void kernel_launch(void* const* d_in, const int* in_sizes, int n_in,
                              void* d_out, int out_size) {
    const float* bt    = (const float*)d_in[0];
    const int*   si    = (const int*)  d_in[1];
    const int*   pi    = (const int*)  d_in[2];
    const float* rmask = (const float*)d_in[3];
    const float* lmask = (const float*)d_in[4];
    const float* stok  = (const float*)d_in[5];
    const float* etok  = (const float*)d_in[6];
    const float* Vw1 = (const float*)d_in[7],  *Vb1 = (const float*)d_in[8];
    const float* Vw2 = (const float*)d_in[9],  *Vb2 = (const float*)d_in[10];
    const float* Ew1 = (const float*)d_in[11], *Eb1 = (const float*)d_in[12];
    const float* Ew2 = (const float*)d_in[13], *Eb2 = (const float*)d_in[14];
    const float* Pw1 = (const float*)d_in[15], *Pb1 = (const float*)d_in[16];
    const float* Pw2 = (const float*)d_in[17], *Pb2 = (const float*)d_in[18];
    const float* Cw1 = (const float*)d_in[19], *Cb1 = (const float*)d_in[20];
    const float* Cw2 = (const float*)d_in[21], *Cb2 = (const float*)d_in[22];
    const float* Aw1 = (const float*)d_in[23], *Ab1 = (const float*)d_in[24];
    const float* Aw2 = (const float*)d_in[25], *Ab2 = (const float*)d_in[26];
    float* hid = (float*)d_out;

    const int smem = (BR * XS + HID * XS + BR * HS) * (int)sizeof(float);
    cudaFuncSetAttribute(mlp5_k<128, 0, 0>, cudaFuncAttributeMaxDynamicSharedMemorySize, smem);
    cudaFuncSetAttribute(mlp5_k<256, 1, 0>, cudaFuncAttributeMaxDynamicSharedMemorySize, smem);
    cudaFuncSetAttribute(mlp5_k<256, 1, 1>, cudaFuncAttributeMaxDynamicSharedMemorySize, smem);
    cudaFuncSetAttribute(mlp5_k<384, 2, 0>, cudaFuncAttributeMaxDynamicSharedMemorySize, smem);

    edge_const_k<<<1, 256>>>(Ew1, Eb1, Ew2, Eb2);
    fold_bias_k<<<1, 256>>>(Pw1, Pb1, Cw1, Cb1);
    zero_cnt_k<<<(2 * NN + 255) / 256, 256>>>();
    count_k<<<(EE + 255) / 256, 256>>>(si, pi);
    inv_k<<<(2 * NN + 255) / 256, 256>>>();
    prep_w1_k<<<128, 256>>>(Vw1, 128, 0);
    prep_w1_k<<<256, 256>>>(Pw1, 256, 1);
    prep_w1_k<<<256, 256>>>(Cw1, 256, 2);
    prep_w1_k<<<384, 256>>>(Aw1, 384, 3);
    prep_w2_k<<<128, 256>>>(Vw2, 0);
    prep_w2_k<<<128, 256>>>(Pw2, 1);
    prep_w2_k<<<128, 256>>>(Cw2, 2);
    prep_w2_k<<<128, 256>>>(Aw2, 3);

    const int gb = (NN + BR - 1) / BR;

    // hidden = MLP_V(batch_token)
    mlp5_k<128, 0, 0><<<gb, NT, smem>>>(NN, Vb1, Vb2, bt,
                                        nullptr, nullptr, nullptr,
                                        nullptr, nullptr, nullptr, nullptr, hid);
    for (int h = 0; h < 3; h++) {
        // S_p += MLP_P([hid[parent], hid[self]]) scattered by self (edge folded into bias)
        mlp5_k<256, 1, 0><<<gb, NT, smem>>>(EE, nullptr, Pb2, hid,
                                            pi, si, si,
                                            nullptr, nullptr, nullptr, nullptr, nullptr);
        // S_c += MLP_C([hid[self], hid[parent]]) scattered by parent
        mlp5_k<256, 1, 1><<<gb, NT, smem>>>(EE, nullptr, Cb2, hid,
                                            si, pi, pi,
                                            nullptr, nullptr, nullptr, nullptr, nullptr);
        // hidden += MLP_A([hid, Sp*inv + rm*st, Sc*inv + lm*et]); re-zeros Sp/Sc
        mlp5_k<384, 2, 0><<<gb, NT, smem>>>(NN, Ab1, Ab2, hid,
                                            nullptr, nullptr, nullptr,
                                            rmask, lmask, stok, etok, hid);
    }
}

// round 12
// speedup vs baseline: 1.5136x; 1.2818x over previous
#include <cuda_runtime.h>
#include <cstdint>
#include <math.h>

#define NN 250000
#define EE 250000
#define D   128
#define HID 256
#define NT  256
#define BR  64
#define XS  34
#define HS  258

// ---- persistent device scratch ----
__device__ float g_Sp[(size_t)NN * D];    // zero-init; finalize_k re-zeroes each hop
__device__ float g_Sc[(size_t)NN * D];
__device__ float g_SpF[(size_t)NN * D];
__device__ float g_ScF[(size_t)NN * D];
__device__ int   g_cnt[2 * NN];
__device__ float g_inv[2 * NN];
__device__ float g_edge[2 * D];
__device__ float g_b1P[HID];
__device__ float g_b1C[HID];
// transposed weights [N][K]
__device__ float g_w1tV[256 * 128];
__device__ float g_w1tP[256 * 256];
__device__ float g_w1tC[256 * 256];
__device__ float g_w1tA[256 * 384];
__device__ float g_w2tV[128 * 256];
__device__ float g_w2tP[128 * 256];
__device__ float g_w2tC[128 * 256];
__device__ float g_w2tA[128 * 256];

__device__ __forceinline__ void ffma2(uint64_t& acc, uint64_t x, uint64_t w) {
    asm("fma.rn.f32x2 %0, %1, %2, %0;" : "+l"(acc) : "l"(x), "l"(w));
}
__device__ __forceinline__ float sum2(uint64_t v) {
    uint32_t lo, hi;
    asm("mov.b64 {%0,%1}, %2;" : "=r"(lo), "=r"(hi) : "l"(v));
    return __uint_as_float(lo) + __uint_as_float(hi);
}
__device__ __forceinline__ void redadd(float* p, float v) {
    asm volatile("red.global.add.f32 [%0], %1;" :: "l"(p), "f"(v) : "memory");
}
__device__ __forceinline__ uint32_t smem_u32(const void* p) {
    uint32_t a;
    asm("{ .reg .u64 t; cvta.to.shared.u64 t, %1; cvt.u32.u64 %0, t; }" : "=r"(a) : "l"(p));
    return a;
}
__device__ __forceinline__ void cp8(uint32_t s, const void* g) {
    asm volatile("cp.async.ca.shared.global [%0], [%1], 8;" :: "r"(s), "l"(g) : "memory");
}
#define CP_COMMIT() asm volatile("cp.async.commit_group;" ::: "memory")
#define CP_WAIT1()  asm volatile("cp.async.wait_group 1;" ::: "memory")

// ---------------- setup kernels ----------------
__global__ void edge_const_k(const float* __restrict__ Ew1, const float* __restrict__ Eb1,
                             const float* __restrict__ Ew2, const float* __restrict__ Eb2) {
    __shared__ float hin[HID], hout[HID];
    int t = threadIdx.x;
    hin[t]  = fmaxf(Ew1[t] + Eb1[t], 0.f);
    hout[t] = fmaxf(Eb1[t], 0.f);
    __syncthreads();
    if (t < D) {
        float si = 0.f, so = 0.f;
        for (int j = 0; j < HID; j++) { float w = Ew2[j * D + t]; si += hin[j] * w; so += hout[j] * w; }
        g_edge[t]     = fmaxf(si + Eb2[t], 0.f);
        g_edge[D + t] = fmaxf(so + Eb2[t], 0.f);
    }
}
__global__ void fold_bias_k(const float* __restrict__ Pw1, const float* __restrict__ Pb1,
                            const float* __restrict__ Cw1, const float* __restrict__ Cb1) {
    int j = threadIdx.x;
    float sp = Pb1[j], sc = Cb1[j];
    for (int c = 0; c < D; c++) {
        sp += g_edge[D + c] * Pw1[(size_t)(2 * D + c) * HID + j];
        sc += g_edge[c]     * Cw1[(size_t)(2 * D + c) * HID + j];
    }
    g_b1P[j] = sp; g_b1C[j] = sc;
}
__global__ void zero_cnt_k() {
    int i = blockIdx.x * blockDim.x + threadIdx.x;
    if (i < 2 * NN) g_cnt[i] = 0;
}
__global__ void count_k(const int* __restrict__ si, const int* __restrict__ pi) {
    int e = blockIdx.x * blockDim.x + threadIdx.x;
    if (e < EE) { atomicAdd(&g_cnt[si[e]], 1); atomicAdd(&g_cnt[NN + pi[e]], 1); }
}
__global__ void inv_k() {
    int i = blockIdx.x * blockDim.x + threadIdx.x;
    if (i < 2 * NN) g_inv[i] = 1.f / fmaxf((float)g_cnt[i], 1.f);
}
__global__ void prep_w1_k(const float* __restrict__ W, int K, int id) {
    float* dst = id == 0 ? g_w1tV : id == 1 ? g_w1tP : id == 2 ? g_w1tC : g_w1tA;
    int i = blockIdx.x * blockDim.x + threadIdx.x;
    if (i < K * 256) { int k = i >> 8, n = i & 255; dst[(size_t)n * K + k] = W[i]; }
}
__global__ void prep_w2_k(const float* __restrict__ W, int id) {
    float* dst = id == 0 ? g_w2tV : id == 1 ? g_w2tP : id == 2 ? g_w2tC : g_w2tA;
    int i = blockIdx.x * blockDim.x + threadIdx.x;
    if (i < 256 * 128) { int k = i >> 7, n = i & 127; dst[(size_t)n * 256 + k] = W[i]; }
}
// SpF = Sp*inv + rm*st ; ScF = Sc*inv + lm*et ; zero Sp, Sc
__global__ void finalize_k(const float* __restrict__ rmask, const float* __restrict__ lmask,
                           const float* __restrict__ stok, const float* __restrict__ etok) {
    int i = blockIdx.x * blockDim.x + threadIdx.x;
    if (i >= NN * 32) return;
    int row = i >> 5, q = i & 31;
    float ivp = g_inv[row], ivc = g_inv[NN + row];
    float rm = rmask[row], lm = lmask[row];
    float4 st = ((const float4*)stok)[q], et = ((const float4*)etok)[q];
    float4 z = make_float4(0.f, 0.f, 0.f, 0.f);
    float4 s = ((float4*)g_Sp)[i];
    float4 o;
    o.x = fmaf(s.x, ivp, rm * st.x); o.y = fmaf(s.y, ivp, rm * st.y);
    o.z = fmaf(s.z, ivp, rm * st.z); o.w = fmaf(s.w, ivp, rm * st.w);
    ((float4*)g_SpF)[i] = o; ((float4*)g_Sp)[i] = z;
    s = ((float4*)g_Sc)[i];
    o.x = fmaf(s.x, ivc, lm * et.x); o.y = fmaf(s.y, ivc, lm * et.y);
    o.z = fmaf(s.z, ivc, lm * et.z); o.w = fmaf(s.w, ivc, lm * et.w);
    ((float4*)g_ScF)[i] = o; ((float4*)g_Sc)[i] = z;
}

// ---------------------------------------------------------------------------
// Fused 2-layer MLP — R10 compute micro-kernel (256 thr, 8 rows/warp, FFMA2),
// staging via cp.async double-buffered pipeline (X and W).
// MODE 0: X = srcA rows (K=128);       out: dst = y
// MODE 1: X = [hid[idxA], hid[idxB]];  out: red-scatter into Sp/Sc by idxB
// MODE 2: X = [hid, SpF, ScF] (K=384); out: dst += y
// ---------------------------------------------------------------------------
#define OFF_X   0          // 2 x 8704
#define OFF_W   17408      // 2 x 34816
#define OFF_H   87040      // 66048
#define OFF_IDX 153088     // 128 ints
#define SMEMSZ  153600

template <int KIN, int MODE, int TGT>
__global__ __launch_bounds__(NT, 1) void mlp6_k(
    int rows,
    const float* __restrict__ B1a, const float* __restrict__ B2,
    const float* __restrict__ srcA,
    const int* __restrict__ idxA, const int* __restrict__ idxB,
    float* __restrict__ dst)
{
    extern __shared__ char smc[];
    float* Hs = (float*)(smc + OFF_H);
    int*   sA = (int*)(smc + OFF_IDX);
    int*   sB = sA + BR;
    const uint32_t smb = smem_u32(smc);

    constexpr int NCH = KIN / 32;
    const float* W1T = MODE == 0 ? g_w1tV : MODE == 2 ? g_w1tA : (TGT == 0 ? g_w1tP : g_w1tC);
    const float* W2T = MODE == 0 ? g_w2tV : MODE == 2 ? g_w2tA : (TGT == 0 ? g_w2tP : g_w2tC);
    const float* B1  = (MODE == 1) ? (TGT == 0 ? (const float*)g_b1P : (const float*)g_b1C) : B1a;

    const int tid = threadIdx.x;
    const int wid = tid >> 5, lane = tid & 31;
    const int row0 = blockIdx.x * BR;

    if (MODE == 1 && tid < 2 * BR) {
        int r = tid & (BR - 1);
        int gr = row0 + r; if (gr >= rows) gr = rows - 1;
        if (tid < BR) sA[r] = idxA[gr]; else sB[r] = idxB[gr];
    }
    __syncthreads();

    auto stageA = [&](int c) {
        uint32_t xd = smb + OFF_X + (c & 1) * 8704;
        uint32_t wd = smb + OFF_W + (c & 1) * 34816;
        // X: 64 rows x 16 float2
#pragma unroll
        for (int i = 0; i < 4; i++) {
            int e = tid + i * NT;
            int r = e >> 4, s = e & 15;
            int gr = row0 + r; if (gr >= rows) gr = rows - 1;
            const float* src;
            if (MODE == 0) {
                src = srcA + (size_t)gr * D + c * 32 + s * 2;
            } else if (MODE == 1) {
                int idx = (c < 4 ? sA[r] : sB[r]);
                src = srcA + (size_t)idx * D + (c & 3) * 32 + s * 2;
            } else {
                const float* base = (c < 4) ? srcA : (c < 8) ? (const float*)g_SpF : (const float*)g_ScF;
                src = base + (size_t)gr * D + (c & 3) * 32 + s * 2;
            }
            cp8(xd + r * 136 + s * 8, src);
        }
        // W1: 256 n x 16 float2
#pragma unroll
        for (int i = 0; i < 16; i++) {
            int e = tid + i * NT;
            int n = e >> 4, s = e & 15;
            cp8(wd + n * 136 + s * 8, W1T + (size_t)n * KIN + c * 32 + s * 2);
        }
    };
    auto stageB = [&](int c) {
        uint32_t wd = smb + OFF_W + (c & 1) * 34816;
#pragma unroll
        for (int i = 0; i < 8; i++) {
            int e = tid + i * NT;
            int n = e >> 4, s = e & 15;
            cp8(wd + n * 136 + s * 8, W2T + (size_t)n * 256 + c * 32 + s * 2);
        }
    };

    // ---------------- phase A: H = relu(X @ W1 + b1), N=256 ----------------
    uint64_t acc[8][8];
#pragma unroll
    for (int i = 0; i < 8; i++)
#pragma unroll
        for (int m = 0; m < 8; m++) acc[i][m] = 0ull;

    stageA(0); CP_COMMIT();
    for (int c = 0; c < NCH; c++) {
        if (c + 1 < NCH) stageA(c + 1);
        CP_COMMIT();
        CP_WAIT1();
        __syncthreads();
        const float* Xb = (const float*)(smc + OFF_X + (c & 1) * 8704);
        const float* Wb = (const float*)(smc + OFF_W + (c & 1) * 34816);
#pragma unroll
        for (int kp = 0; kp < 16; kp++) {
            uint64_t xp[8];
#pragma unroll
            for (int i = 0; i < 8; i++)
                xp[i] = *(const uint64_t*)&Xb[(wid * 8 + i) * XS + kp * 2];
#pragma unroll
            for (int m = 0; m < 8; m++) {
                uint64_t wv = *(const uint64_t*)&Wb[(m * 32 + lane) * XS + kp * 2];
#pragma unroll
                for (int i = 0; i < 8; i++) ffma2(acc[i][m], xp[i], wv);
            }
        }
        __syncthreads();
    }

    // prefetch first W2 chunk, overlap with epilogue A
    stageB(0); CP_COMMIT();

    // epilogue A -> Hs
#pragma unroll
    for (int m = 0; m < 8; m++) {
        int col = m * 32 + lane;
        float b = B1[col];
#pragma unroll
        for (int i = 0; i < 8; i++)
            Hs[(wid * 8 + i) * HS + col] = fmaxf(sum2(acc[i][m]) + b, 0.f);
    }

    // ---------------- phase B: Y = relu(H @ W2 + b2), N=128 ----------------
    uint64_t acc2[8][4];
#pragma unroll
    for (int i = 0; i < 8; i++)
#pragma unroll
        for (int m = 0; m < 4; m++) acc2[i][m] = 0ull;

    for (int c = 0; c < 8; c++) {
        if (c + 1 < 8) stageB(c + 1);
        CP_COMMIT();
        CP_WAIT1();
        __syncthreads();
        const float* Wb = (const float*)(smc + OFF_W + (c & 1) * 34816);
#pragma unroll
        for (int kp = 0; kp < 16; kp++) {
            uint64_t xp[8];
#pragma unroll
            for (int i = 0; i < 8; i++)
                xp[i] = *(const uint64_t*)&Hs[(wid * 8 + i) * HS + c * 32 + kp * 2];
#pragma unroll
            for (int m = 0; m < 4; m++) {
                uint64_t wv = *(const uint64_t*)&Wb[(m * 32 + lane) * XS + kp * 2];
#pragma unroll
                for (int i = 0; i < 8; i++) ffma2(acc2[i][m], xp[i], wv);
            }
        }
        __syncthreads();
    }

    // ---------------- epilogue B ----------------
#pragma unroll
    for (int i = 0; i < 8; i++) {
        int r = wid * 8 + i;
        int gr = row0 + r;
        if (gr >= rows) continue;
#pragma unroll
        for (int m = 0; m < 4; m++) {
            int col = m * 32 + lane;
            float y = fmaxf(sum2(acc2[i][m]) + B2[col], 0.f);
            if (MODE == 1) {
                redadd((TGT == 0 ? g_Sp : g_Sc) + (size_t)sB[r] * D + col, y);
            } else if (MODE == 0) {
                dst[(size_t)gr * D + col] = y;
            } else {
                size_t o = (size_t)gr * D + col;
                dst[o] = dst[o] + y;
            }
        }
    }
}

// ---------------------------------------------------------------------------
extern "C" void kernel_launch(void* const* d_in, const int* in_sizes, int n_in,
                              void* d_out, int out_size) {
    const float* bt    = (const float*)d_in[0];
    const int*   si    = (const int*)  d_in[1];
    const int*   pi    = (const int*)  d_in[2];
    const float* rmask = (const float*)d_in[3];
    const float* lmask = (const float*)d_in[4];
    const float* stok  = (const float*)d_in[5];
    const float* etok  = (const float*)d_in[6];
    const float* Vw1 = (const float*)d_in[7],  *Vb1 = (const float*)d_in[8];
    const float* Vw2 = (const float*)d_in[9],  *Vb2 = (const float*)d_in[10];
    const float* Ew1 = (const float*)d_in[11], *Eb1 = (const float*)d_in[12];
    const float* Ew2 = (const float*)d_in[13], *Eb2 = (const float*)d_in[14];
    const float* Pw1 = (const float*)d_in[15], *Pb1 = (const float*)d_in[16];
    const float* Pw2 = (const float*)d_in[17], *Pb2 = (const float*)d_in[18];
    const float* Cw1 = (const float*)d_in[19], *Cb1 = (const float*)d_in[20];
    const float* Cw2 = (const float*)d_in[21], *Cb2 = (const float*)d_in[22];
    const float* Aw1 = (const float*)d_in[23], *Ab1 = (const float*)d_in[24];
    const float* Aw2 = (const float*)d_in[25], *Ab2 = (const float*)d_in[26];
    float* hid = (float*)d_out;

    cudaFuncSetAttribute(mlp6_k<128, 0, 0>, cudaFuncAttributeMaxDynamicSharedMemorySize, SMEMSZ);
    cudaFuncSetAttribute(mlp6_k<256, 1, 0>, cudaFuncAttributeMaxDynamicSharedMemorySize, SMEMSZ);
    cudaFuncSetAttribute(mlp6_k<256, 1, 1>, cudaFuncAttributeMaxDynamicSharedMemorySize, SMEMSZ);
    cudaFuncSetAttribute(mlp6_k<384, 2, 0>, cudaFuncAttributeMaxDynamicSharedMemorySize, SMEMSZ);

    edge_const_k<<<1, 256>>>(Ew1, Eb1, Ew2, Eb2);
    fold_bias_k<<<1, 256>>>(Pw1, Pb1, Cw1, Cb1);
    zero_cnt_k<<<(2 * NN + 255) / 256, 256>>>();
    count_k<<<(EE + 255) / 256, 256>>>(si, pi);
    inv_k<<<(2 * NN + 255) / 256, 256>>>();
    prep_w1_k<<<128, 256>>>(Vw1, 128, 0);
    prep_w1_k<<<256, 256>>>(Pw1, 256, 1);
    prep_w1_k<<<256, 256>>>(Cw1, 256, 2);
    prep_w1_k<<<384, 256>>>(Aw1, 384, 3);
    prep_w2_k<<<128, 256>>>(Vw2, 0);
    prep_w2_k<<<128, 256>>>(Pw2, 1);
    prep_w2_k<<<128, 256>>>(Cw2, 2);
    prep_w2_k<<<128, 256>>>(Aw2, 3);

    const int gb = (NN + BR - 1) / BR;
    mlp6_k<128, 0, 0><<<gb, NT, SMEMSZ>>>(NN, Vb1, Vb2, bt, nullptr, nullptr, hid);
    for (int h = 0; h < 3; h++) {
        mlp6_k<256, 1, 0><<<gb, NT, SMEMSZ>>>(EE, nullptr, Pb2, hid, pi, si, nullptr);
        mlp6_k<256, 1, 1><<<gb, NT, SMEMSZ>>>(EE, nullptr, Cb2, hid, si, pi, nullptr);
        finalize_k<<<(NN * 32 + 255) / 256, 256>>>(rmask, lmask, stok, etok);
        mlp6_k<384, 2, 0><<<gb, NT, SMEMSZ>>>(NN, Ab1, Ab2, hid, nullptr, nullptr, hid);
    }
}